// round 1
// baseline (speedup 1.0000x reference)
#include <cuda_runtime.h>
#include <math.h>

#define GS 480
#define IMS 384
#define NCH 16
#define KPTS 500000
#define PAD 48
#define HALF 240

// Scratch (allocation-free: __device__ globals)
__device__ float2 g_buf1[NCH * GS * GS];   // [c][k][x] after pass 1 (transposed write)
__device__ float2 g_buf2[GS * GS * NCH];   // [kx][ky][c] after pass 2
__device__ float2 g_w480[GS];
__device__ float2 g_w32[32];
__device__ float2 g_w15[15];

__global__ void init_tables_kernel() {
    int t = threadIdx.x;
    if (t < GS) {
        double ang = -2.0 * (double)t / (double)GS;  // in units of pi
        g_w480[t] = make_float2((float)cospi(ang), (float)sinpi(ang));
    }
    if (t < 32) {
        double ang = -2.0 * (double)t / 32.0;
        g_w32[t] = make_float2((float)cospi(ang), (float)sinpi(ang));
    }
    if (t < 15) {
        double ang = -2.0 * (double)t / 15.0;
        g_w15[t] = make_float2((float)cospi(ang), (float)sinpi(ang));
    }
}

// Four-step 480-pt DFT: 480 = 32 * 15.
//   n = n1 + 32*n2   (n1 in [0,32), n2 in [0,15))
//   k = k2 + 15*k1   (k1 in [0,32), k2 in [0,15))
//   A[n1,k2]  = sum_n2 w15[n2*k2] * x[n1 + 32*n2]
//   A'[n1,k2] = A[n1,k2] * w480[n1*k2]
//   X[k2+15*k1] = sum_n1 w32[n1*k1] * A'[n1,k2]
// Thread t in step1: k2 = t>>5, n1 = t&31 (warp shares k2).
// Thread t in step3: k2p = t>>5, k1 = t&31 (warp shares k2p -> smem broadcast).
// Returns value in *res, output bin index via *gk.
__device__ __forceinline__ void fft480_core(
    const float2* __restrict__ xs,      // smem input, 480
    float2* __restrict__ As,            // smem scratch, 15*33 (padded stride)
    const float2* __restrict__ w15s,    // smem table 15
    const float2* __restrict__ w32s,    // smem table 32
    int t, float2* res, int* gk)
{
    int n1 = t & 31;
    int k2 = t >> 5;
    float2 acc = make_float2(0.f, 0.f);
    int wi = 0;
    #pragma unroll
    for (int n2 = 0; n2 < 15; n2++) {
        float2 w  = w15s[wi];
        float2 xv = xs[n1 + 32 * n2];
        acc.x = fmaf(w.x, xv.x, fmaf(-w.y, xv.y, acc.x));
        acc.y = fmaf(w.x, xv.y, fmaf( w.y, xv.x, acc.y));
        wi += k2; if (wi >= 15) wi -= 15;
    }
    float2 tw = g_w480[n1 * k2];   // n1*k2 <= 31*14 = 434 < 480
    float2 a2;
    a2.x = tw.x * acc.x - tw.y * acc.y;
    a2.y = tw.x * acc.y + tw.y * acc.x;
    As[k2 * 33 + n1] = a2;
    __syncthreads();

    int k1  = t & 31;
    int k2p = t >> 5;
    float2 r = make_float2(0.f, 0.f);
    int wj = 0;
    #pragma unroll
    for (int m = 0; m < 32; m++) {
        float2 w  = w32s[wj];
        float2 av = As[k2p * 33 + m];   // broadcast within warp
        r.x = fmaf(w.x, av.x, fmaf(-w.y, av.y, r.x));
        r.y = fmaf(w.x, av.y, fmaf( w.y, av.x, r.y));
        wj = (wj + k1) & 31;
    }
    *res = r;
    *gk  = 15 * k1 + k2p;
}

// Pass 1: FFT along Y. One block per (c, x) padded+shifted row.
// Writes transposed: buf1[c][ky][x].
__global__ __launch_bounds__(480) void pass1_kernel(
    const float* __restrict__ img_re, const float* __restrict__ img_im)
{
    __shared__ float2 xs[GS];
    __shared__ float2 As[15 * 33];
    __shared__ float2 w15s[15];
    __shared__ float2 w32s[32];

    int b = blockIdx.x;
    int c = b / GS;
    int x = b - c * GS;
    int t = threadIdx.x;

    if (t < 15) w15s[t] = g_w15[t];
    if (t < 32) w32s[t] = g_w32[t];

    // ifftshift along x (row selector) + center pad
    int px = x + HALF; if (px >= GS) px -= GS;
    int ix = px - PAD;
    bool rowv = ((unsigned)ix < (unsigned)IMS);

    // ifftshift along y (element) + center pad
    int py = t + HALF; if (py >= GS) py -= GS;
    int iy = py - PAD;

    float2 v = make_float2(0.f, 0.f);
    if (rowv && (unsigned)iy < (unsigned)IMS) {
        int o = (c * IMS + ix) * IMS + iy;
        v.x = img_re[o];
        v.y = img_im[o];
    }
    xs[t] = v;
    __syncthreads();

    float2 r; int gk;
    fft480_core(xs, As, w15s, w32s, t, &r, &gk);

    g_buf1[(c * GS + gk) * GS + x] = r;
}

// Pass 2: FFT along X. One block per (c, ky). Loads coalesced rows of buf1.
// Writes buf2[kx][ky][c] with 1/480 ortho scale.
__global__ __launch_bounds__(480) void pass2_kernel()
{
    __shared__ float2 xs[GS];
    __shared__ float2 As[15 * 33];
    __shared__ float2 w15s[15];
    __shared__ float2 w32s[32];

    int b  = blockIdx.x;
    int c  = b / GS;
    int ky = b - c * GS;
    int t  = threadIdx.x;

    if (t < 15) w15s[t] = g_w15[t];
    if (t < 32) w32s[t] = g_w32[t];

    xs[t] = g_buf1[(c * GS + ky) * GS + t];
    __syncthreads();

    float2 r; int gk;
    fft480_core(xs, As, w15s, w32s, t, &r, &gk);

    const float s = 1.0f / 480.0f;   // ortho norm for 480x480
    g_buf2[(gk * GS + ky) * NCH + c] = make_float2(r.x * s, r.y * s);
}

// Gather: one thread per trajectory point, all 16 channels (128B contiguous).
__global__ __launch_bounds__(256) void gather_kernel(
    const float* __restrict__ trj, float* __restrict__ out)
{
    int k = blockIdx.x * blockDim.x + threadIdx.x;
    if (k >= KPTS) return;

    float tx = trj[2 * k + 0];
    float ty = trj[2 * k + 1];
    // replicate reference exactly: t*1.25, +240, clip [0,479], round-half-even
    float fx = __fadd_rn(__fmul_rn(tx, 1.25f), 240.0f);
    float fy = __fadd_rn(__fmul_rn(ty, 1.25f), 240.0f);
    fx = fminf(fmaxf(fx, 0.0f), 479.0f);
    fy = fminf(fmaxf(fy, 0.0f), 479.0f);
    int ix = (int)rintf(fx);
    int iy = (int)rintf(fy);

    // fftshift on the spectrum: shifted[i] = unshifted[(i+240)%480]
    int ux = ix + HALF; if (ux >= GS) ux -= GS;
    int uy = iy + HALF; if (uy >= GS) uy -= GS;

    const float4* p = reinterpret_cast<const float4*>(g_buf2 + (ux * GS + uy) * NCH);
    #pragma unroll
    for (int q = 0; q < 8; q++) {
        float4 v = p[q];                  // channels 2q, 2q+1 (re,im,re,im)
        int c0 = 2 * q;
        out[(c0    ) * KPTS + k] = v.x;   // real plane
        out[(16 + c0) * KPTS + k] = v.y;  // imag plane
        out[(c0 + 1 ) * KPTS + k] = v.z;
        out[(17 + c0) * KPTS + k] = v.w;
    }
}

extern "C" void kernel_launch(void* const* d_in, const int* in_sizes, int n_in,
                              void* d_out, int out_size)
{
    const float* img_re = (const float*)d_in[0];   // (1,16,384,384)
    const float* img_im = (const float*)d_in[1];   // (1,16,384,384)
    const float* trj    = (const float*)d_in[2];   // (1,500000,2)
    float* out = (float*)d_out;                    // (2,1,16,500000)

    init_tables_kernel<<<1, GS>>>();
    pass1_kernel<<<NCH * GS, GS>>>(img_re, img_im);
    pass2_kernel<<<NCH * GS, GS>>>();
    gather_kernel<<<(KPTS + 255) / 256, 256>>>(trj, out);
}

// round 2
// speedup vs baseline: 1.4812x; 1.4812x over previous
#include <cuda_runtime.h>
#include <math.h>

#define GS 480
#define IMS 384
#define NCH 16
#define KPTS 500000
#define PAD 48
#define HALF 240
#define R 8                    // rows (FFTs) per block
#define SH_STRIDE 496          // float2 stride per row in shared scratch

// Scratch (allocation-free: __device__ globals)
__device__ float2 g_buf1[NCH * GS * GS];   // [c][ky][x] after pass 1
__device__ float2 g_buf2[GS * GS * NCH];   // [kx][ky][c] after pass 2

// Four-step 480-pt DFT: 480 = 32 * 15.
//   n = n1 + 32*n2   (n1 in [0,32), n2 in [0,15))
//   k = k2 + 15*k1   (k1 in [0,32), k2 in [0,15))
// Batched over R rows: sh holds R rows of 480 float2 (stride SH_STRIDE),
// and is overwritten in-place by the intermediate A' matrix (15x33 padded).
// SKIP: skip n2 in {6,7,8} (input zeros from center padding, pass 1 only).
// Returns output bin index gk; results in res[R].
template<bool SKIP>
__device__ __forceinline__ int fft480_batch(
    float2* __restrict__ sh,
    const float2* __restrict__ w15s,
    const float2* __restrict__ w32s,
    int t, float2 res[R])
{
    const int n1 = t & 31;
    const int k2 = t >> 5;

    float2 acc[R];
    #pragma unroll
    for (int r = 0; r < R; r++) acc[r] = make_float2(0.f, 0.f);

    int wi = 0;
    #pragma unroll
    for (int n2 = 0; n2 < 15; n2++) {
        if (!SKIP || (n2 < 6 || n2 > 8)) {
            float2 w = w15s[wi];
            #pragma unroll
            for (int r = 0; r < R; r++) {
                float2 xv = sh[r * SH_STRIDE + n1 + 32 * n2];
                acc[r].x = fmaf(w.x, xv.x, fmaf(-w.y, xv.y, acc[r].x));
                acc[r].y = fmaf(w.x, xv.y, fmaf( w.y, xv.x, acc[r].y));
            }
        }
        wi += k2; if (wi >= 15) wi -= 15;
    }

    // twiddle w480^(n1*k2), computed on the fly
    float sa, ca;
    sincospif((float)(n1 * k2) * (-1.0f / 240.0f), &sa, &ca);
    #pragma unroll
    for (int r = 0; r < R; r++) {
        float2 a2;
        a2.x = ca * acc[r].x - sa * acc[r].y;
        a2.y = ca * acc[r].y + sa * acc[r].x;
        acc[r] = a2;
    }

    __syncthreads();   // everyone done reading xs before overwrite
    #pragma unroll
    for (int r = 0; r < R; r++)
        sh[r * SH_STRIDE + k2 * 33 + n1] = acc[r];   // max idx 493 < 496
    __syncthreads();

    const int k1 = n1, k2p = k2;
    #pragma unroll
    for (int r = 0; r < R; r++) res[r] = make_float2(0.f, 0.f);

    int wj = 0;
    #pragma unroll 4
    for (int m = 0; m < 32; m++) {
        float2 w = w32s[wj];
        #pragma unroll
        for (int r = 0; r < R; r++) {
            float2 av = sh[r * SH_STRIDE + k2p * 33 + m];  // warp broadcast
            res[r].x = fmaf(w.x, av.x, fmaf(-w.y, av.y, res[r].x));
            res[r].y = fmaf(w.x, av.y, fmaf( w.y, av.x, res[r].y));
        }
        wj = (wj + k1) & 31;
    }
    return 15 * k1 + k2p;
}

__device__ __forceinline__ void build_tables(int t, float2* w15s, float2* w32s, float sc)
{
    if (t < 15) { float s, c; sincospif(-2.0f * (float)t / 15.0f, &s, &c); w15s[t] = make_float2(c, s); }
    if (t < 32) { float s, c; sincospif(-(float)t / 16.0f, &s, &c); w32s[t] = make_float2(c * sc, s * sc); }
}

// Pass 1: FFT along Y. One block per (c, 8 x-rows). Writes buf1[c][ky][x].
__global__ __launch_bounds__(480, 2) void pass1_kernel(
    const float* __restrict__ img_re, const float* __restrict__ img_im)
{
    __shared__ float2 sh[R * SH_STRIDE];
    __shared__ float2 w15s[15];
    __shared__ float2 w32s[32];

    const int t = threadIdx.x;
    const int b = blockIdx.x;
    const int c  = b / (GS / R);
    const int xg = (b - c * (GS / R)) * R;

    build_tables(t, w15s, w32s, 1.0f);

    // ifftshift along y (element) + center pad
    int py = t + HALF; if (py >= GS) py -= GS;
    int iy = py - PAD;
    bool colv = ((unsigned)iy < (unsigned)IMS);

    #pragma unroll
    for (int r = 0; r < R; r++) {
        int x = xg + r;
        int px = x + HALF; if (px >= GS) px -= GS;
        int ix = px - PAD;
        float2 v = make_float2(0.f, 0.f);
        if (colv && (unsigned)ix < (unsigned)IMS) {
            int o = (c * IMS + ix) * IMS + iy;
            v.x = img_re[o];
            v.y = img_im[o];
        }
        sh[r * SH_STRIDE + t] = v;
    }
    __syncthreads();

    float2 res[R];
    int gk = fft480_batch<true>(sh, w15s, w32s, t, res);

    float2* dst = &g_buf1[(c * GS + gk) * GS + xg];
    #pragma unroll
    for (int r = 0; r < R; r++) dst[r] = res[r];   // 64B contiguous per thread
}

// Pass 2: FFT along X. One block per (c, 8 ky-rows). Writes buf2[kx][ky][c], scaled.
__global__ __launch_bounds__(480, 2) void pass2_kernel()
{
    __shared__ float2 sh[R * SH_STRIDE];
    __shared__ float2 w15s[15];
    __shared__ float2 w32s[32];

    const int t = threadIdx.x;
    const int b = blockIdx.x;
    const int c  = b / (GS / R);
    const int kg = (b - c * (GS / R)) * R;

    build_tables(t, w15s, w32s, 1.0f / 480.0f);  // fold ortho norm into step 3

    #pragma unroll
    for (int r = 0; r < R; r++)
        sh[r * SH_STRIDE + t] = g_buf1[(c * GS + (kg + r)) * GS + t];
    __syncthreads();

    float2 res[R];
    int gk = fft480_batch<false>(sh, w15s, w32s, t, res);

    #pragma unroll
    for (int r = 0; r < R; r++)
        g_buf2[(gk * GS + (kg + r)) * NCH + c] = res[r];
}

// Gather: one thread per trajectory point, all 16 channels (128B contiguous).
__global__ __launch_bounds__(256) void gather_kernel(
    const float* __restrict__ trj, float* __restrict__ out)
{
    int k = blockIdx.x * blockDim.x + threadIdx.x;
    if (k >= KPTS) return;

    float tx = trj[2 * k + 0];
    float ty = trj[2 * k + 1];
    // replicate reference exactly: t*1.25, +240, clip [0,479], round-half-even
    float fx = __fadd_rn(__fmul_rn(tx, 1.25f), 240.0f);
    float fy = __fadd_rn(__fmul_rn(ty, 1.25f), 240.0f);
    fx = fminf(fmaxf(fx, 0.0f), 479.0f);
    fy = fminf(fmaxf(fy, 0.0f), 479.0f);
    int ix = (int)rintf(fx);
    int iy = (int)rintf(fy);

    // fftshift on the spectrum: shifted[i] = unshifted[(i+240)%480]
    int ux = ix + HALF; if (ux >= GS) ux -= GS;
    int uy = iy + HALF; if (uy >= GS) uy -= GS;

    const float4* p = reinterpret_cast<const float4*>(g_buf2 + (ux * GS + uy) * NCH);
    #pragma unroll
    for (int q = 0; q < 8; q++) {
        float4 v = p[q];                  // channels 2q, 2q+1 (re,im,re,im)
        int c0 = 2 * q;
        out[(c0     ) * KPTS + k] = v.x;  // real plane
        out[(16 + c0) * KPTS + k] = v.y;  // imag plane
        out[(c0 + 1  ) * KPTS + k] = v.z;
        out[(17 + c0) * KPTS + k] = v.w;
    }
}

extern "C" void kernel_launch(void* const* d_in, const int* in_sizes, int n_in,
                              void* d_out, int out_size)
{
    const float* img_re = (const float*)d_in[0];   // (1,16,384,384)
    const float* img_im = (const float*)d_in[1];   // (1,16,384,384)
    const float* trj    = (const float*)d_in[2];   // (1,500000,2)
    float* out = (float*)d_out;                    // (2,1,16,500000)

    pass1_kernel<<<NCH * (GS / R), GS>>>(img_re, img_im);
    pass2_kernel<<<NCH * (GS / R), GS>>>();
    gather_kernel<<<(KPTS + 255) / 256, 256>>>(trj, out);
}

// round 3
// speedup vs baseline: 1.9113x; 1.2904x over previous
#include <cuda_runtime.h>
#include <math.h>

#define GS 480
#define IMS 384
#define NCH 16
#define KPTS 500000
#define PAD 48
#define HALF 240
#define R 8                    // rows (FFTs) per block
#define SH_STRIDE 480          // float2 stride per row in shared input

// Scratch (allocation-free: __device__ globals)
__device__ float2 g_buf1[NCH * GS * GS];   // [c][ky][x] after pass 1
__device__ float2 g_buf2[GS * GS * NCH];   // [kx][ky][c] after pass 2

__device__ __forceinline__ float2 cmulf(float2 a, float2 b) {
    return make_float2(a.x * b.x - a.y * b.y, a.x * b.y + a.y * b.x);
}

// One radix-2 DIF butterfly stage across lanes (half-distance H), with twiddle tw
// (tw = exp(-pi*i*(lane&(H-1))/H), only used by upper lanes).
template<int H>
__device__ __forceinline__ void bfly(float2& v, float2 tw, int lane) {
    float ox = __shfl_xor_sync(0xffffffffu, v.x, H);
    float oy = __shfl_xor_sync(0xffffffffu, v.y, H);
    if (lane & H) {
        v = cmulf(make_float2(ox - v.x, oy - v.y), tw);
    } else {
        v = make_float2(v.x + ox, v.y + oy);
    }
}

// 480-pt DFT, four-step 480 = 32 * 15:
//   n = n1 + 32*n2, k = k2 + 15*k1
//   step1 (smem): A[n1,k2]  = sum_n2 w15[n2*k2] * x[n1+32*n2]   (thread: n1=lane, k2=warp)
//   twiddle:      A'[n1,k2] = A[n1,k2] * w480[n1*k2]
//   step3 (regs): 32-pt FFT over n1 within each warp via shfl butterflies
//                 (DIF -> output bit-reversed: lane holds X[15*brev5(lane)+k2])
// SKIP: skip n2 in {6,7,8} (zeros from center padding, pass 1 only).
template<bool SKIP>
__device__ __forceinline__ int fft480_batch(
    const float2* __restrict__ sh,      // R rows x 480 input (read-only here)
    const float2* __restrict__ w15s,
    int t, float2 v[R])
{
    const int n1 = t & 31;
    const int k2 = t >> 5;

    float2 acc[R];
    #pragma unroll
    for (int r = 0; r < R; r++) acc[r] = make_float2(0.f, 0.f);

    int wi = 0;
    #pragma unroll
    for (int n2 = 0; n2 < 15; n2++) {
        if (!SKIP || (n2 < 6 || n2 > 8)) {
            float2 w = w15s[wi];
            #pragma unroll
            for (int r = 0; r < R; r++) {
                float2 xv = sh[r * SH_STRIDE + n1 + 32 * n2];
                acc[r].x = fmaf(w.x, xv.x, fmaf(-w.y, xv.y, acc[r].x));
                acc[r].y = fmaf(w.x, xv.y, fmaf( w.y, xv.x, acc[r].y));
            }
        }
        wi += k2; if (wi >= 15) wi -= 15;
    }

    // inter-step twiddle w480^(n1*k2)
    float sa, ca;
    sincospif((float)(n1 * k2) * (-1.0f / 240.0f), &sa, &ca);
    float2 tw0 = make_float2(ca, sa);
    #pragma unroll
    for (int r = 0; r < R; r++) v[r] = cmulf(acc[r], tw0);

    // per-stage butterfly twiddles (depend only on lane)
    float2 t16, t8, t4, t2;
    { float s, c; sincospif(-(float)(n1 & 15) * (1.0f / 16.0f), &s, &c); t16 = make_float2(c, s); }
    { float s, c; sincospif(-(float)(n1 &  7) * (1.0f /  8.0f), &s, &c); t8  = make_float2(c, s); }
    { float s, c; sincospif(-(float)(n1 &  3) * (1.0f /  4.0f), &s, &c); t4  = make_float2(c, s); }
    { float s, c; sincospif(-(float)(n1 &  1) * (1.0f /  2.0f), &s, &c); t2  = make_float2(c, s); }

    #pragma unroll
    for (int r = 0; r < R; r++) {
        bfly<16>(v[r], t16, n1);
        bfly<8> (v[r], t8,  n1);
        bfly<4> (v[r], t4,  n1);
        bfly<2> (v[r], t2,  n1);
        // H=1: twiddle == 1
        float ox = __shfl_xor_sync(0xffffffffu, v[r].x, 1);
        float oy = __shfl_xor_sync(0xffffffffu, v[r].y, 1);
        v[r] = (n1 & 1) ? make_float2(ox - v[r].x, oy - v[r].y)
                        : make_float2(v[r].x + ox, v[r].y + oy);
    }

    int k1 = (int)(__brev((unsigned)n1) >> 27);   // brev5
    return 15 * k1 + k2;
}

__device__ __forceinline__ void build_w15(int t, float2* w15s, float sc)
{
    if (t < 15) {
        float s, c; sincospif(-2.0f * (float)t / 15.0f, &s, &c);
        w15s[t] = make_float2(c * sc, s * sc);
    }
}

// Pass 1: FFT along Y. One block per (c, 8 x-rows). Writes buf1[c][ky][x].
__global__ __launch_bounds__(480, 2) void pass1_kernel(
    const float* __restrict__ img_re, const float* __restrict__ img_im)
{
    __shared__ float2 sh[R * SH_STRIDE];
    __shared__ float2 w15s[15];

    const int t = threadIdx.x;
    const int b = blockIdx.x;
    const int c  = b / (GS / R);
    const int xg = (b - c * (GS / R)) * R;

    build_w15(t, w15s, 1.0f);

    // ifftshift along y (element) + center pad
    int py = t + HALF; if (py >= GS) py -= GS;
    int iy = py - PAD;
    bool colv = ((unsigned)iy < (unsigned)IMS);

    #pragma unroll
    for (int r = 0; r < R; r++) {
        int x = xg + r;
        int px = x + HALF; if (px >= GS) px -= GS;
        int ix = px - PAD;
        float2 v = make_float2(0.f, 0.f);
        if (colv && (unsigned)ix < (unsigned)IMS) {
            int o = (c * IMS + ix) * IMS + iy;
            v.x = img_re[o];
            v.y = img_im[o];
        }
        sh[r * SH_STRIDE + t] = v;
    }
    __syncthreads();

    float2 res[R];
    int gk = fft480_batch<true>(sh, w15s, t, res);

    float2* dst = &g_buf1[(c * GS + gk) * GS + xg];
    #pragma unroll
    for (int r = 0; r < R; r++) dst[r] = res[r];   // 64B contiguous per thread
}

// Pass 2: FFT along X. One block per (c, 8 ky-rows). Writes buf2[kx][ky][c], scaled.
__global__ __launch_bounds__(480, 2) void pass2_kernel()
{
    __shared__ float2 sh[R * SH_STRIDE];
    __shared__ float2 w15s[15];

    const int t = threadIdx.x;
    const int b = blockIdx.x;
    const int c  = b / (GS / R);
    const int kg = (b - c * (GS / R)) * R;

    build_w15(t, w15s, 1.0f / 480.0f);  // fold ortho norm into step 1 weights

    #pragma unroll
    for (int r = 0; r < R; r++)
        sh[r * SH_STRIDE + t] = g_buf1[(c * GS + (kg + r)) * GS + t];
    __syncthreads();

    float2 res[R];
    int gk = fft480_batch<false>(sh, w15s, t, res);

    #pragma unroll
    for (int r = 0; r < R; r++)
        g_buf2[(gk * GS + (kg + r)) * NCH + c] = res[r];
}

// Gather: one thread per trajectory point, all 16 channels (128B contiguous).
__global__ __launch_bounds__(256) void gather_kernel(
    const float* __restrict__ trj, float* __restrict__ out)
{
    int k = blockIdx.x * blockDim.x + threadIdx.x;
    if (k >= KPTS) return;

    float tx = trj[2 * k + 0];
    float ty = trj[2 * k + 1];
    // replicate reference exactly: t*1.25, +240, clip [0,479], round-half-even
    float fx = __fadd_rn(__fmul_rn(tx, 1.25f), 240.0f);
    float fy = __fadd_rn(__fmul_rn(ty, 1.25f), 240.0f);
    fx = fminf(fmaxf(fx, 0.0f), 479.0f);
    fy = fminf(fmaxf(fy, 0.0f), 479.0f);
    int ix = (int)rintf(fx);
    int iy = (int)rintf(fy);

    // fftshift on the spectrum: shifted[i] = unshifted[(i+240)%480]
    int ux = ix + HALF; if (ux >= GS) ux -= GS;
    int uy = iy + HALF; if (uy >= GS) uy -= GS;

    const float4* p = reinterpret_cast<const float4*>(g_buf2 + (ux * GS + uy) * NCH);
    #pragma unroll
    for (int q = 0; q < 8; q++) {
        float4 v = p[q];                  // channels 2q, 2q+1 (re,im,re,im)
        int c0 = 2 * q;
        out[(c0     ) * KPTS + k] = v.x;  // real plane
        out[(16 + c0) * KPTS + k] = v.y;  // imag plane
        out[(c0 + 1  ) * KPTS + k] = v.z;
        out[(17 + c0) * KPTS + k] = v.w;
    }
}

extern "C" void kernel_launch(void* const* d_in, const int* in_sizes, int n_in,
                              void* d_out, int out_size)
{
    const float* img_re = (const float*)d_in[0];   // (1,16,384,384)
    const float* img_im = (const float*)d_in[1];   // (1,16,384,384)
    const float* trj    = (const float*)d_in[2];   // (1,500000,2)
    float* out = (float*)d_out;                    // (2,1,16,500000)

    pass1_kernel<<<NCH * (GS / R), GS>>>(img_re, img_im);
    pass2_kernel<<<NCH * (GS / R), GS>>>();
    gather_kernel<<<(KPTS + 255) / 256, 256>>>(trj, out);
}

// round 4
// speedup vs baseline: 2.4125x; 1.2622x over previous
#include <cuda_runtime.h>
#include <math.h>

#define GS 480
#define IMS 384
#define NCH 16
#define KPTS 500000
#define PAD 48
#define HALF 240
#define NW 8            // warps (rows) per block
#define NT 256

// Scratch (allocation-free: __device__ globals)
__device__ float2 g_buf1[NCH * GS * GS];   // [c][ky][x] after pass 1 (x in [192,288) never written/read)
__device__ float2 g_buf2[GS * GS * NCH];   // [kx][ky][c] after pass 2

__device__ __forceinline__ float2 cmulf(float2 a, float2 b) {
    return make_float2(a.x * b.x - a.y * b.y, a.x * b.y + a.y * b.x);
}

// One radix-2 DIF butterfly stage across lanes (distance H), twiddle tw used by upper lanes.
template<int H>
__device__ __forceinline__ void bfly(float2& v, float2 tw, int lane) {
    float ox = __shfl_xor_sync(0xffffffffu, v.x, H);
    float oy = __shfl_xor_sync(0xffffffffu, v.y, H);
    if (lane & H) v = cmulf(make_float2(ox - v.x, oy - v.y), tw);
    else          v = make_float2(v.x + ox, v.y + oy);
}

struct BT { float2 t16, t8, t4, t2, base; };

__device__ __forceinline__ BT make_bt(int lane) {
    BT bt; float s, c;
    sincospif(-(float)(lane & 15) * (1.0f / 16.0f), &s, &c); bt.t16 = make_float2(c, s);
    sincospif(-(float)(lane &  7) * (1.0f /  8.0f), &s, &c); bt.t8  = make_float2(c, s);
    sincospif(-(float)(lane &  3) * (1.0f /  4.0f), &s, &c); bt.t4  = make_float2(c, s);
    sincospif(-(float)(lane &  1) * (1.0f /  2.0f), &s, &c); bt.t2  = make_float2(c, s);
    sincospif(-(float)lane * (1.0f / 240.0f), &s, &c);        bt.base = make_float2(c, s);  // w480^lane
    return bt;
}

// One k2 slice of the 480-pt four-step DFT (480 = 32*15), warp-per-row.
// xv[12]: x[n1 + 32*n2] for n2 in {0..5, 9..14} (n2 6..8 are zero / never read).
// Returns X[15*brev5(n1) + k2] in this lane (butterflies output bit-reversed).
__device__ __forceinline__ float2 fft_k2_slice(
    const float2 xv[12], const float2* __restrict__ w15s,
    int k2, float2 tw, const BT& bt, int lane)
{
    float2 acc = make_float2(0.f, 0.f);
    int wi = 0;
    #pragma unroll
    for (int n2 = 0; n2 < 15; n2++) {
        if (n2 < 6 || n2 > 8) {
            int j = (n2 < 6) ? n2 : n2 - 3;        // compile-time per unrolled iter
            float2 w = w15s[wi];                    // uniform address -> broadcast
            float2 x = xv[j];
            acc.x = fmaf(w.x, x.x, fmaf(-w.y, x.y, acc.x));
            acc.y = fmaf(w.x, x.y, fmaf( w.y, x.x, acc.y));
        }
        wi += k2; if (wi >= 15) wi -= 15;
    }
    acc = cmulf(acc, tw);                           // inter-step twiddle w480^(n1*k2)

    bfly<16>(acc, bt.t16, lane);
    bfly<8> (acc, bt.t8,  lane);
    bfly<4> (acc, bt.t4,  lane);
    bfly<2> (acc, bt.t2,  lane);
    float ox = __shfl_xor_sync(0xffffffffu, acc.x, 1);
    float oy = __shfl_xor_sync(0xffffffffu, acc.y, 1);
    acc = (lane & 1) ? make_float2(ox - acc.x, oy - acc.y)
                     : make_float2(acc.x + ox, acc.y + oy);
    return acc;
}

// Pass 1: FFT along Y for the 384 nonzero x-rows. One warp per row.
// Writes buf1[c][ky][x] via shared staging (coalesced 64B chunks).
__global__ __launch_bounds__(NT) void pass1_kernel(
    const float* __restrict__ img_re, const float* __restrict__ img_im)
{
    __shared__ float2 sh[GS * 9];      // [ky][8 rows], stride 9 (conflict degree 2)
    __shared__ float2 w15s[15];

    const int t = threadIdx.x, lane = t & 31, w = t >> 5;
    const int b = blockIdx.x;
    const int c = b / 48;
    const int g = b - c * 48;
    int x0 = g * 8; if (x0 >= 192) x0 += 96;       // valid x: [0,192) U [288,480)

    if (t < 15) {
        float s, cc; sincospif(-2.0f * (float)t / 15.0f, &s, &cc);
        w15s[t] = make_float2(cc, s);
    }
    __syncthreads();

    const int x = x0 + w;
    int px = x + HALF; if (px >= GS) px -= GS;
    const int ix = px - PAD;                        // guaranteed in [0,384)
    const float* rre = img_re + (c * IMS + ix) * IMS;
    const float* rim = img_im + (c * IMS + ix) * IMS;

    float2 xv[12];
    #pragma unroll
    for (int j = 0; j < 12; j++) {
        int n2 = (j < 6) ? j : j + 3;
        int n = lane + 32 * n2;
        int py = n + HALF; if (py >= GS) py -= GS;
        int iy = py - PAD;                          // guaranteed in [0,384)
        xv[j].x = rre[iy];
        xv[j].y = rim[iy];
    }

    const BT bt = make_bt(lane);
    const int k1 = (int)(__brev((unsigned)lane) >> 27);
    float2 tw = make_float2(1.f, 0.f);
    #pragma unroll 3
    for (int k2 = 0; k2 < 15; k2++) {
        float2 v = fft_k2_slice(xv, w15s, k2, tw, bt, lane);
        sh[(15 * k1 + k2) * 9 + w] = v;
        tw = cmulf(tw, bt.base);
    }
    __syncthreads();

    #pragma unroll
    for (int idx = t; idx < GS * 8; idx += NT) {
        int ky = idx >> 3, j = idx & 7;
        g_buf1[(c * GS + ky) * GS + x0 + j] = sh[ky * 9 + j];
    }
}

// Pass 2: FFT along X. One warp per ky-row; skips the zero x-band [192,288).
// Writes buf2[kx][ky][c] (scattered 8B, inherent to gather-friendly layout).
__global__ __launch_bounds__(NT) void pass2_kernel()
{
    __shared__ float2 w15s[15];

    const int t = threadIdx.x, lane = t & 31, w = t >> 5;
    const int b = blockIdx.x;
    const int c = b / 60;
    const int kg = (b - c * 60) * 8;
    const int ky = kg + w;

    if (t < 15) {
        float s, cc; sincospif(-2.0f * (float)t / 15.0f, &s, &cc);
        const float sc = 1.0f / 480.0f;             // ortho norm folded here
        w15s[t] = make_float2(cc * sc, s * sc);
    }
    __syncthreads();

    const float2* src = g_buf1 + (c * GS + ky) * GS;
    float2 xv[12];
    #pragma unroll
    for (int j = 0; j < 12; j++) {
        int n2 = (j < 6) ? j : j + 3;
        xv[j] = src[lane + 32 * n2];                // coalesced 256B per n2
    }

    const BT bt = make_bt(lane);
    const int k1 = (int)(__brev((unsigned)lane) >> 27);
    float2 tw = make_float2(1.f, 0.f);
    #pragma unroll 3
    for (int k2 = 0; k2 < 15; k2++) {
        float2 v = fft_k2_slice(xv, w15s, k2, tw, bt, lane);
        g_buf2[((15 * k1 + k2) * GS + ky) * NCH + c] = v;
        tw = cmulf(tw, bt.base);
    }
}

// Gather: two trajectory points per thread -> STG.64 stores.
__global__ __launch_bounds__(256) void gather_kernel(
    const float* __restrict__ trj, float* __restrict__ out)
{
    int p = blockIdx.x * blockDim.x + threadIdx.x;
    int k0 = 2 * p;
    if (k0 >= KPTS) return;

    int u[2];
    #pragma unroll
    for (int q = 0; q < 2; q++) {
        float tx = trj[2 * (k0 + q) + 0];
        float ty = trj[2 * (k0 + q) + 1];
        float fx = __fadd_rn(__fmul_rn(tx, 1.25f), 240.0f);
        float fy = __fadd_rn(__fmul_rn(ty, 1.25f), 240.0f);
        fx = fminf(fmaxf(fx, 0.0f), 479.0f);
        fy = fminf(fmaxf(fy, 0.0f), 479.0f);
        int ix = (int)rintf(fx);
        int iy = (int)rintf(fy);
        int ux = ix + HALF; if (ux >= GS) ux -= GS;
        int uy = iy + HALF; if (uy >= GS) uy -= GS;
        u[q] = (ux * GS + uy) * NCH;
    }

    const float4* pa = reinterpret_cast<const float4*>(g_buf2 + u[0]);
    const float4* pb = reinterpret_cast<const float4*>(g_buf2 + u[1]);
    #pragma unroll
    for (int q = 0; q < 8; q++) {
        float4 a = pa[q];
        float4 b = pb[q];
        int c0 = 2 * q;
        *reinterpret_cast<float2*>(out + (c0     ) * KPTS + k0) = make_float2(a.x, b.x);
        *reinterpret_cast<float2*>(out + (16 + c0) * KPTS + k0) = make_float2(a.y, b.y);
        *reinterpret_cast<float2*>(out + (c0 + 1  ) * KPTS + k0) = make_float2(a.z, b.z);
        *reinterpret_cast<float2*>(out + (17 + c0) * KPTS + k0) = make_float2(a.w, b.w);
    }
}

extern "C" void kernel_launch(void* const* d_in, const int* in_sizes, int n_in,
                              void* d_out, int out_size)
{
    const float* img_re = (const float*)d_in[0];   // (1,16,384,384)
    const float* img_im = (const float*)d_in[1];   // (1,16,384,384)
    const float* trj    = (const float*)d_in[2];   // (1,500000,2)
    float* out = (float*)d_out;                    // (2,1,16,500000)

    pass1_kernel<<<NCH * 48, NT>>>(img_re, img_im);
    pass2_kernel<<<NCH * 60, NT>>>();
    gather_kernel<<<(KPTS / 2 + 255) / 256, 256>>>(trj, out);
}

// round 5
// speedup vs baseline: 2.7655x; 1.1463x over previous
#include <cuda_runtime.h>
#include <math.h>

#define GS 480
#define IMS 384
#define NCH 16
#define KPTS 500000
#define PAD 48
#define HALF 240
#define NT 256

// Scratch (allocation-free: __device__ globals)
__device__ float2 g_buf1[NCH * GS * GS];   // [c][ky][x] after pass 1 (x in [192,288) never touched)
__device__ float2 g_buf2[GS * GS * NCH];   // [kx][ky][c] after pass 2

__device__ __forceinline__ float2 cmulf(float2 a, float2 b) {
    return make_float2(a.x * b.x - a.y * b.y, a.x * b.y + a.y * b.x);
}
__device__ __forceinline__ float2 cadd(float2 a, float2 b) { return make_float2(a.x + b.x, a.y + b.y); }
__device__ __forceinline__ float2 csub(float2 a, float2 b) { return make_float2(a.x - b.x, a.y - b.y); }

// forward DFT-3 (w = exp(-2pi i/3))
__device__ __forceinline__ void dft3(float2 x0, float2 x1, float2 x2,
                                     float2& X0, float2& X1, float2& X2)
{
    const float c = -0.5f, s = -0.86602540378443865f;
    float2 t = cadd(x1, x2);
    float2 d = csub(x1, x2);
    X0 = cadd(x0, t);
    float2 m = make_float2(fmaf(c, t.x, x0.x), fmaf(c, t.y, x0.y));
    float2 e = make_float2(-s * d.y, s * d.x);     // i*s*d
    X1 = cadd(m, e);
    X2 = csub(m, e);
}

// forward DFT-5 (w = exp(-2pi i/5))
__device__ __forceinline__ void dft5(float2 x0, float2 x1, float2 x2, float2 x3, float2 x4,
                                     float2& X0, float2& X1, float2& X2, float2& X3, float2& X4)
{
    const float c1 = 0.30901699437494742f, c2 = -0.80901699437494745f;
    const float s1 = 0.95105651629515353f, s2 =  0.58778525229247314f;
    float2 t1 = cadd(x1, x4), t2 = cadd(x2, x3);
    float2 t3 = csub(x1, x4), t4 = csub(x2, x3);
    X0 = cadd(x0, cadd(t1, t2));
    float2 m1 = make_float2(fmaf(c1, t1.x, fmaf(c2, t2.x, x0.x)),
                            fmaf(c1, t1.y, fmaf(c2, t2.y, x0.y)));
    float2 m2 = make_float2(fmaf(c2, t1.x, fmaf(c1, t2.x, x0.x)),
                            fmaf(c2, t1.y, fmaf(c1, t2.y, x0.y)));
    float2 u1 = make_float2(fmaf(s1, t3.x,  s2 * t4.x), fmaf(s1, t3.y,  s2 * t4.y));
    float2 u2 = make_float2(fmaf(s2, t3.x, -s1 * t4.x), fmaf(s2, t3.y, -s1 * t4.y));
    X1 = make_float2(m1.x + u1.y, m1.y - u1.x);    // m1 - i*u1
    X4 = make_float2(m1.x - u1.y, m1.y + u1.x);    // m1 + i*u1
    X2 = make_float2(m2.x + u2.y, m2.y - u2.x);    // m2 - i*u2
    X3 = make_float2(m2.x - u2.y, m2.y + u2.x);    // m2 + i*u2
}

// Full 15-point DFT over n2 via PFA (15 = 3*5, CRT maps, no inter-twiddles).
// Inputs xv[j] = x[n2] with n2 = j (j<6) or j+3 (j>=6); n2 in {6,7,8} are zero.
// Outputs A[k2] = sum_n2 x[n2] * exp(-2pi i n2 k2 / 15), natural k2 order.
__device__ __forceinline__ void dft15_pfa(const float2 xv[12], float2 A[15])
{
    const float2 Z = make_float2(0.f, 0.f);
    float2 y0[5], y1[5], y2[5];                    // y[ka][b]
    // input map n = (5a + 3b) mod 15
    dft3(xv[0], xv[5], xv[7],  y0[0], y1[0], y2[0]);   // b=0: n=0,5,10
    dft3(xv[3], Z,     xv[10], y0[1], y1[1], y2[1]);   // b=1: n=3,(8),13
    dft3(Z,     xv[8], xv[1],  y0[2], y1[2], y2[2]);   // b=2: n=(6),11,1
    dft3(xv[6], xv[11],xv[4],  y0[3], y1[3], y2[3]);   // b=3: n=9,14,4
    dft3(xv[9], xv[2], Z,      y0[4], y1[4], y2[4]);   // b=4: n=12,2,(7)
    // output map k = (10*ka + 6*kb) mod 15
    dft5(y0[0], y0[1], y0[2], y0[3], y0[4], A[0],  A[6],  A[12], A[3],  A[9]);
    dft5(y1[0], y1[1], y1[2], y1[3], y1[4], A[10], A[1],  A[7],  A[13], A[4]);
    dft5(y2[0], y2[1], y2[2], y2[3], y2[4], A[5],  A[11], A[2],  A[8],  A[14]);
}

// One radix-2 DIF butterfly stage across lanes (distance H), twiddle tw used by upper lanes.
template<int H>
__device__ __forceinline__ void bfly(float2& v, float2 tw, int lane) {
    float ox = __shfl_xor_sync(0xffffffffu, v.x, H);
    float oy = __shfl_xor_sync(0xffffffffu, v.y, H);
    if (lane & H) v = cmulf(make_float2(ox - v.x, oy - v.y), tw);
    else          v = make_float2(v.x + ox, v.y + oy);
}

struct BT { float2 t16, t8, t4, t2, base; };

__device__ __forceinline__ BT make_bt(int lane) {
    BT bt; float s, c;
    sincospif(-(float)(lane & 15) * (1.0f / 16.0f), &s, &c); bt.t16 = make_float2(c, s);
    sincospif(-(float)(lane &  7) * (1.0f /  8.0f), &s, &c); bt.t8  = make_float2(c, s);
    sincospif(-(float)(lane &  3) * (1.0f /  4.0f), &s, &c); bt.t4  = make_float2(c, s);
    sincospif(-(float)(lane &  1) * (1.0f /  2.0f), &s, &c); bt.t2  = make_float2(c, s);
    sincospif(-(float)lane * (1.0f / 240.0f), &s, &c);        bt.base = make_float2(c, s);  // w480^lane
    return bt;
}

// 32-pt FFT across lanes for one k2 slice (input v pre-twiddled).
__device__ __forceinline__ float2 fft32_lanes(float2 v, const BT& bt, int lane)
{
    bfly<16>(v, bt.t16, lane);
    bfly<8> (v, bt.t8,  lane);
    bfly<4> (v, bt.t4,  lane);
    bfly<2> (v, bt.t2,  lane);
    float ox = __shfl_xor_sync(0xffffffffu, v.x, 1);
    float oy = __shfl_xor_sync(0xffffffffu, v.y, 1);
    return (lane & 1) ? make_float2(ox - v.x, oy - v.y)
                      : make_float2(v.x + ox, v.y + oy);
}

// Pass 1: FFT along Y for the 384 nonzero x-rows. One warp per row.
// Writes buf1[c][ky][x] via shared staging (coalesced 64B chunks).
__global__ __launch_bounds__(NT) void pass1_kernel(
    const float* __restrict__ img_re, const float* __restrict__ img_im)
{
    __shared__ float2 sh[GS * 9];      // [ky][8 rows], stride 9

    const int t = threadIdx.x, lane = t & 31, w = t >> 5;
    const int b = blockIdx.x;
    const int c = b / 48;
    const int g = b - c * 48;
    int x0 = g * 8; if (x0 >= 192) x0 += 96;       // valid x: [0,192) U [288,480)

    const int x = x0 + w;
    int px = x + HALF; if (px >= GS) px -= GS;
    const int ix = px - PAD;                        // in [0,384)
    const float* rre = img_re + (c * IMS + ix) * IMS;
    const float* rim = img_im + (c * IMS + ix) * IMS;

    float2 xv[12];
    #pragma unroll
    for (int j = 0; j < 12; j++) {
        int n2 = (j < 6) ? j : j + 3;
        int n = lane + 32 * n2;
        int py = n + HALF; if (py >= GS) py -= GS;
        int iy = py - PAD;                          // in [0,384)
        xv[j].x = rre[iy];
        xv[j].y = rim[iy];
    }

    float2 A[15];
    dft15_pfa(xv, A);

    const BT bt = make_bt(lane);
    const int k1 = (int)(__brev((unsigned)lane) >> 27);
    float2 tw = make_float2(1.f, 0.f);
    #pragma unroll
    for (int k2 = 0; k2 < 15; k2++) {
        float2 v = fft32_lanes(cmulf(A[k2], tw), bt, lane);
        sh[(15 * k1 + k2) * 9 + w] = v;
        tw = cmulf(tw, bt.base);
    }
    __syncthreads();

    #pragma unroll
    for (int idx = t; idx < GS * 8; idx += NT) {
        int ky = idx >> 3, j = idx & 7;
        g_buf1[(c * GS + ky) * GS + x0 + j] = sh[ky * 9 + j];
    }
}

// Pass 2: FFT along X. One warp per ky-row; skips the zero x-band [192,288).
// Writes buf2[kx][ky][c] with ortho norm folded into the twiddle chain seed.
__global__ __launch_bounds__(NT) void pass2_kernel()
{
    const int t = threadIdx.x, lane = t & 31, w = t >> 5;
    const int b = blockIdx.x;
    const int c = b / 60;
    const int ky = (b - c * 60) * 8 + w;

    const float2* src = g_buf1 + (c * GS + ky) * GS;
    float2 xv[12];
    #pragma unroll
    for (int j = 0; j < 12; j++) {
        int n2 = (j < 6) ? j : j + 3;
        xv[j] = src[lane + 32 * n2];                // coalesced 256B per n2
    }

    float2 A[15];
    dft15_pfa(xv, A);

    const BT bt = make_bt(lane);
    const int k1 = (int)(__brev((unsigned)lane) >> 27);
    float2 tw = make_float2(1.0f / 480.0f, 0.f);    // ortho norm seed
    #pragma unroll
    for (int k2 = 0; k2 < 15; k2++) {
        float2 v = fft32_lanes(cmulf(A[k2], tw), bt, lane);
        g_buf2[((15 * k1 + k2) * GS + ky) * NCH + c] = v;
        tw = cmulf(tw, bt.base);
    }
}

// Gather: two trajectory points per thread -> STG.64 stores.
__global__ __launch_bounds__(256) void gather_kernel(
    const float* __restrict__ trj, float* __restrict__ out)
{
    int p = blockIdx.x * blockDim.x + threadIdx.x;
    int k0 = 2 * p;
    if (k0 >= KPTS) return;

    int u[2];
    #pragma unroll
    for (int q = 0; q < 2; q++) {
        float tx = trj[2 * (k0 + q) + 0];
        float ty = trj[2 * (k0 + q) + 1];
        float fx = __fadd_rn(__fmul_rn(tx, 1.25f), 240.0f);
        float fy = __fadd_rn(__fmul_rn(ty, 1.25f), 240.0f);
        fx = fminf(fmaxf(fx, 0.0f), 479.0f);
        fy = fminf(fmaxf(fy, 0.0f), 479.0f);
        int ix = (int)rintf(fx);
        int iy = (int)rintf(fy);
        int ux = ix + HALF; if (ux >= GS) ux -= GS;
        int uy = iy + HALF; if (uy >= GS) uy -= GS;
        u[q] = (ux * GS + uy) * NCH;
    }

    const float4* pa = reinterpret_cast<const float4*>(g_buf2 + u[0]);
    const float4* pb = reinterpret_cast<const float4*>(g_buf2 + u[1]);
    #pragma unroll
    for (int q = 0; q < 8; q++) {
        float4 a = pa[q];
        float4 b = pb[q];
        int c0 = 2 * q;
        *reinterpret_cast<float2*>(out + (c0     ) * KPTS + k0) = make_float2(a.x, b.x);
        *reinterpret_cast<float2*>(out + (16 + c0) * KPTS + k0) = make_float2(a.y, b.y);
        *reinterpret_cast<float2*>(out + (c0 + 1  ) * KPTS + k0) = make_float2(a.z, b.z);
        *reinterpret_cast<float2*>(out + (17 + c0) * KPTS + k0) = make_float2(a.w, b.w);
    }
}

extern "C" void kernel_launch(void* const* d_in, const int* in_sizes, int n_in,
                              void* d_out, int out_size)
{
    const float* img_re = (const float*)d_in[0];   // (1,16,384,384)
    const float* img_im = (const float*)d_in[1];   // (1,16,384,384)
    const float* trj    = (const float*)d_in[2];   // (1,500000,2)
    float* out = (float*)d_out;                    // (2,1,16,500000)

    pass1_kernel<<<NCH * 48, NT>>>(img_re, img_im);
    pass2_kernel<<<NCH * 60, NT>>>();
    gather_kernel<<<(KPTS / 2 + 255) / 256, 256>>>(trj, out);
}

// round 6
// speedup vs baseline: 3.5167x; 1.2717x over previous
#include <cuda_runtime.h>
#include <math.h>

#define GS 480
#define IMS 384
#define NCH 16
#define KPTS 500000
#define PAD 48
#define HALF 240
#define NT 256
#define HPLANE (GS * GS * 8)     // float2 elements per half-channel plane

// Scratch (allocation-free: __device__ globals)
__device__ float2 g_buf1[NCH * GS * GS];     // [c][ky][x] after pass 1 (x in [192,288) never touched)
__device__ float2 g_buf2[2 * HPLANE];        // [h][kx][ky][c8] after pass 2

__device__ __forceinline__ float2 cmulf(float2 a, float2 b) {
    return make_float2(a.x * b.x - a.y * b.y, a.x * b.y + a.y * b.x);
}
__device__ __forceinline__ float2 cadd(float2 a, float2 b) { return make_float2(a.x + b.x, a.y + b.y); }
__device__ __forceinline__ float2 csub(float2 a, float2 b) { return make_float2(a.x - b.x, a.y - b.y); }

// forward DFT-3 (w = exp(-2pi i/3))
__device__ __forceinline__ void dft3(float2 x0, float2 x1, float2 x2,
                                     float2& X0, float2& X1, float2& X2)
{
    const float c = -0.5f, s = -0.86602540378443865f;
    float2 t = cadd(x1, x2);
    float2 d = csub(x1, x2);
    X0 = cadd(x0, t);
    float2 m = make_float2(fmaf(c, t.x, x0.x), fmaf(c, t.y, x0.y));
    float2 e = make_float2(-s * d.y, s * d.x);     // i*s*d
    X1 = cadd(m, e);
    X2 = csub(m, e);
}

// forward DFT-5 (w = exp(-2pi i/5))
__device__ __forceinline__ void dft5(float2 x0, float2 x1, float2 x2, float2 x3, float2 x4,
                                     float2& X0, float2& X1, float2& X2, float2& X3, float2& X4)
{
    const float c1 = 0.30901699437494742f, c2 = -0.80901699437494745f;
    const float s1 = 0.95105651629515353f, s2 =  0.58778525229247314f;
    float2 t1 = cadd(x1, x4), t2 = cadd(x2, x3);
    float2 t3 = csub(x1, x4), t4 = csub(x2, x3);
    X0 = cadd(x0, cadd(t1, t2));
    float2 m1 = make_float2(fmaf(c1, t1.x, fmaf(c2, t2.x, x0.x)),
                            fmaf(c1, t1.y, fmaf(c2, t2.y, x0.y)));
    float2 m2 = make_float2(fmaf(c2, t1.x, fmaf(c1, t2.x, x0.x)),
                            fmaf(c2, t1.y, fmaf(c1, t2.y, x0.y)));
    float2 u1 = make_float2(fmaf(s1, t3.x,  s2 * t4.x), fmaf(s1, t3.y,  s2 * t4.y));
    float2 u2 = make_float2(fmaf(s2, t3.x, -s1 * t4.x), fmaf(s2, t3.y, -s1 * t4.y));
    X1 = make_float2(m1.x + u1.y, m1.y - u1.x);    // m1 - i*u1
    X4 = make_float2(m1.x - u1.y, m1.y + u1.x);    // m1 + i*u1
    X2 = make_float2(m2.x + u2.y, m2.y - u2.x);    // m2 - i*u2
    X3 = make_float2(m2.x - u2.y, m2.y + u2.x);    // m2 + i*u2
}

// Full 15-point DFT over n2 via PFA (15 = 3*5, CRT maps, no inter-twiddles).
// Inputs xv[j] = x[n2] with n2 = j (j<6) or j+3 (j>=6); n2 in {6,7,8} are zero.
__device__ __forceinline__ void dft15_pfa(const float2 xv[12], float2 A[15])
{
    const float2 Z = make_float2(0.f, 0.f);
    float2 y0[5], y1[5], y2[5];                    // y[ka][b]
    // input map n = (5a + 3b) mod 15
    dft3(xv[0], xv[5], xv[7],  y0[0], y1[0], y2[0]);   // b=0: n=0,5,10
    dft3(xv[3], Z,     xv[10], y0[1], y1[1], y2[1]);   // b=1: n=3,(8),13
    dft3(Z,     xv[8], xv[1],  y0[2], y1[2], y2[2]);   // b=2: n=(6),11,1
    dft3(xv[6], xv[11],xv[4],  y0[3], y1[3], y2[3]);   // b=3: n=9,14,4
    dft3(xv[9], xv[2], Z,      y0[4], y1[4], y2[4]);   // b=4: n=12,2,(7)
    // output map k = (10*ka + 6*kb) mod 15
    dft5(y0[0], y0[1], y0[2], y0[3], y0[4], A[0],  A[6],  A[12], A[3],  A[9]);
    dft5(y1[0], y1[1], y1[2], y1[3], y1[4], A[10], A[1],  A[7],  A[13], A[4]);
    dft5(y2[0], y2[1], y2[2], y2[3], y2[4], A[5],  A[11], A[2],  A[8],  A[14]);
}

// One radix-2 DIF butterfly stage across lanes (distance H), twiddle tw used by upper lanes.
template<int H>
__device__ __forceinline__ void bfly(float2& v, float2 tw, int lane) {
    float ox = __shfl_xor_sync(0xffffffffu, v.x, H);
    float oy = __shfl_xor_sync(0xffffffffu, v.y, H);
    if (lane & H) v = cmulf(make_float2(ox - v.x, oy - v.y), tw);
    else          v = make_float2(v.x + ox, v.y + oy);
}

struct BT { float2 t16, t8, t4, t2, base; };

__device__ __forceinline__ BT make_bt(int lane) {
    BT bt; float s, c;
    sincospif(-(float)(lane & 15) * (1.0f / 16.0f), &s, &c); bt.t16 = make_float2(c, s);
    sincospif(-(float)(lane &  7) * (1.0f /  8.0f), &s, &c); bt.t8  = make_float2(c, s);
    sincospif(-(float)(lane &  3) * (1.0f /  4.0f), &s, &c); bt.t4  = make_float2(c, s);
    sincospif(-(float)(lane &  1) * (1.0f /  2.0f), &s, &c); bt.t2  = make_float2(c, s);
    sincospif(-(float)lane * (1.0f / 240.0f), &s, &c);        bt.base = make_float2(c, s);  // w480^lane
    return bt;
}

// 32-pt FFT across lanes for one k2 slice (input v pre-twiddled). Output bit-reversed.
__device__ __forceinline__ float2 fft32_lanes(float2 v, const BT& bt, int lane)
{
    bfly<16>(v, bt.t16, lane);
    bfly<8> (v, bt.t8,  lane);
    bfly<4> (v, bt.t4,  lane);
    bfly<2> (v, bt.t2,  lane);
    float ox = __shfl_xor_sync(0xffffffffu, v.x, 1);
    float oy = __shfl_xor_sync(0xffffffffu, v.y, 1);
    return (lane & 1) ? make_float2(ox - v.x, oy - v.y)
                      : make_float2(v.x + ox, v.y + oy);
}

// Pass 1: FFT along Y for the 384 nonzero x-rows. One warp per row.
// Writes buf1[c][ky][x] via shared staging (coalesced 64B chunks).
__global__ __launch_bounds__(NT) void pass1_kernel(
    const float* __restrict__ img_re, const float* __restrict__ img_im)
{
    __shared__ float2 sh[GS * 9];      // [ky][8 rows], stride 9

    const int t = threadIdx.x, lane = t & 31, w = t >> 5;
    const int b = blockIdx.x;
    const int c = b / 48;
    const int g = b - c * 48;
    int x0 = g * 8; if (x0 >= 192) x0 += 96;       // valid x: [0,192) U [288,480)

    const int x = x0 + w;
    int px = x + HALF; if (px >= GS) px -= GS;
    const int ix = px - PAD;                        // in [0,384)
    const float* rre = img_re + (c * IMS + ix) * IMS;
    const float* rim = img_im + (c * IMS + ix) * IMS;

    float2 xv[12];
    #pragma unroll
    for (int j = 0; j < 12; j++) {
        int n2 = (j < 6) ? j : j + 3;
        int n = lane + 32 * n2;
        int py = n + HALF; if (py >= GS) py -= GS;
        int iy = py - PAD;                          // in [0,384)
        xv[j].x = rre[iy];
        xv[j].y = rim[iy];
    }

    float2 A[15];
    dft15_pfa(xv, A);

    const BT bt = make_bt(lane);
    const int k1 = (int)(__brev((unsigned)lane) >> 27);
    float2 tw = make_float2(1.f, 0.f);
    #pragma unroll
    for (int k2 = 0; k2 < 15; k2++) {
        float2 v = fft32_lanes(cmulf(A[k2], tw), bt, lane);
        sh[(15 * k1 + k2) * 9 + w] = v;
        tw = cmulf(tw, bt.base);
    }
    __syncthreads();

    #pragma unroll
    for (int idx = t; idx < GS * 8; idx += NT) {
        int ky = idx >> 3, j = idx & 7;
        g_buf1[(c * GS + ky) * GS + x0 + j] = sh[ky * 9 + j];
    }
}

// Pass 2: FFT along X. Block = (ky, half); 8 warps = 8 channels of one ky row.
// Stages in shared, writes buf2[h][kx][ky][c8] as dense 64B runs.
__global__ __launch_bounds__(NT) void pass2_kernel()
{
    __shared__ float2 sh[GS * 9];      // [kx][8 channels], stride 9

    const int t = threadIdx.x, lane = t & 31, w = t >> 5;
    const int b = blockIdx.x;
    const int ky = b >> 1;
    const int h  = b & 1;
    const int c  = h * 8 + w;

    const float2* src = g_buf1 + (c * GS + ky) * GS;
    float2 xv[12];
    #pragma unroll
    for (int j = 0; j < 12; j++) {
        int n2 = (j < 6) ? j : j + 3;
        xv[j] = src[lane + 32 * n2];                // coalesced 256B per n2
    }

    float2 A[15];
    dft15_pfa(xv, A);

    const BT bt = make_bt(lane);
    const int k1 = (int)(__brev((unsigned)lane) >> 27);
    float2 tw = make_float2(1.0f / 480.0f, 0.f);    // ortho norm seed
    #pragma unroll
    for (int k2 = 0; k2 < 15; k2++) {
        float2 v = fft32_lanes(cmulf(A[k2], tw), bt, lane);
        sh[(15 * k1 + k2) * 9 + w] = v;
        tw = cmulf(tw, bt.base);
    }
    __syncthreads();

    float2* dst = g_buf2 + h * HPLANE + ky * 8;     // [kx][ky][c8]
    #pragma unroll
    for (int idx = t; idx < GS * 8; idx += NT) {
        int kx = idx >> 3, lc = idx & 7;
        dst[kx * (GS * 8) + lc] = sh[kx * 9 + lc];  // 64B runs per kx
    }
}

// Gather: four trajectory points per thread -> float4 loads and stores.
__global__ __launch_bounds__(256) void gather_kernel(
    const float* __restrict__ trj, float* __restrict__ out)
{
    int p = blockIdx.x * blockDim.x + threadIdx.x;
    int k0 = 4 * p;
    if (k0 >= KPTS) return;

    int u[4];
    #pragma unroll
    for (int q = 0; q < 4; q++) {
        float tx = trj[2 * (k0 + q) + 0];
        float ty = trj[2 * (k0 + q) + 1];
        float fx = __fadd_rn(__fmul_rn(tx, 1.25f), 240.0f);
        float fy = __fadd_rn(__fmul_rn(ty, 1.25f), 240.0f);
        fx = fminf(fmaxf(fx, 0.0f), 479.0f);
        fy = fminf(fmaxf(fy, 0.0f), 479.0f);
        int ix = (int)rintf(fx);
        int iy = (int)rintf(fy);
        int ux = ix + HALF; if (ux >= GS) ux -= GS;
        int uy = iy + HALF; if (uy >= GS) uy -= GS;
        u[q] = (ux * GS + uy) * 8;
    }

    #pragma unroll
    for (int h = 0; h < 2; h++) {
        const float2* plane = g_buf2 + h * HPLANE;
        const float4* pa = reinterpret_cast<const float4*>(plane + u[0]);
        const float4* pb = reinterpret_cast<const float4*>(plane + u[1]);
        const float4* pc = reinterpret_cast<const float4*>(plane + u[2]);
        const float4* pd = reinterpret_cast<const float4*>(plane + u[3]);
        #pragma unroll
        for (int j = 0; j < 4; j++) {
            float4 a = pa[j], b = pb[j], c = pc[j], d = pd[j];
            int c0 = h * 8 + 2 * j;
            *reinterpret_cast<float4*>(out + (c0     ) * KPTS + k0) = make_float4(a.x, b.x, c.x, d.x);
            *reinterpret_cast<float4*>(out + (16 + c0) * KPTS + k0) = make_float4(a.y, b.y, c.y, d.y);
            *reinterpret_cast<float4*>(out + (c0 + 1  ) * KPTS + k0) = make_float4(a.z, b.z, c.z, d.z);
            *reinterpret_cast<float4*>(out + (17 + c0) * KPTS + k0) = make_float4(a.w, b.w, c.w, d.w);
        }
    }
}

extern "C" void kernel_launch(void* const* d_in, const int* in_sizes, int n_in,
                              void* d_out, int out_size)
{
    const float* img_re = (const float*)d_in[0];   // (1,16,384,384)
    const float* img_im = (const float*)d_in[1];   // (1,16,384,384)
    const float* trj    = (const float*)d_in[2];   // (1,500000,2)
    float* out = (float*)d_out;                    // (2,1,16,500000)

    pass1_kernel<<<NCH * 48, NT>>>(img_re, img_im);
    pass2_kernel<<<GS * 2, NT>>>();
    gather_kernel<<<(KPTS / 4 + 255) / 256, 256>>>(trj, out);
}

// round 7
// speedup vs baseline: 3.6608x; 1.0410x over previous
#include <cuda_runtime.h>
#include <math.h>

#define GS 480
#define IMS 384
#define NCH 16
#define KPTS 500000
#define PAD 48
#define HALF 240
#define NT 256
#define GPTS 128                 // gather points per block
#define HPLANE (GS * GS * 8)     // float2 elements per half-channel plane

// Scratch (allocation-free: __device__ globals)
__device__ float2 g_buf1[NCH * GS * GS];     // [c][ky][x] after pass 1 (x in [192,288) never touched)
__device__ float2 g_buf2[2 * HPLANE];        // [h][kx][ky][c8] after pass 2

__device__ __forceinline__ float2 cmulf(float2 a, float2 b) {
    return make_float2(a.x * b.x - a.y * b.y, a.x * b.y + a.y * b.x);
}
__device__ __forceinline__ float2 cadd(float2 a, float2 b) { return make_float2(a.x + b.x, a.y + b.y); }
__device__ __forceinline__ float2 csub(float2 a, float2 b) { return make_float2(a.x - b.x, a.y - b.y); }

// forward DFT-3 (w = exp(-2pi i/3))
__device__ __forceinline__ void dft3(float2 x0, float2 x1, float2 x2,
                                     float2& X0, float2& X1, float2& X2)
{
    const float c = -0.5f, s = -0.86602540378443865f;
    float2 t = cadd(x1, x2);
    float2 d = csub(x1, x2);
    X0 = cadd(x0, t);
    float2 m = make_float2(fmaf(c, t.x, x0.x), fmaf(c, t.y, x0.y));
    float2 e = make_float2(-s * d.y, s * d.x);     // i*s*d
    X1 = cadd(m, e);
    X2 = csub(m, e);
}

// forward DFT-5 (w = exp(-2pi i/5))
__device__ __forceinline__ void dft5(float2 x0, float2 x1, float2 x2, float2 x3, float2 x4,
                                     float2& X0, float2& X1, float2& X2, float2& X3, float2& X4)
{
    const float c1 = 0.30901699437494742f, c2 = -0.80901699437494745f;
    const float s1 = 0.95105651629515353f, s2 =  0.58778525229247314f;
    float2 t1 = cadd(x1, x4), t2 = cadd(x2, x3);
    float2 t3 = csub(x1, x4), t4 = csub(x2, x3);
    X0 = cadd(x0, cadd(t1, t2));
    float2 m1 = make_float2(fmaf(c1, t1.x, fmaf(c2, t2.x, x0.x)),
                            fmaf(c1, t1.y, fmaf(c2, t2.y, x0.y)));
    float2 m2 = make_float2(fmaf(c2, t1.x, fmaf(c1, t2.x, x0.x)),
                            fmaf(c2, t1.y, fmaf(c1, t2.y, x0.y)));
    float2 u1 = make_float2(fmaf(s1, t3.x,  s2 * t4.x), fmaf(s1, t3.y,  s2 * t4.y));
    float2 u2 = make_float2(fmaf(s2, t3.x, -s1 * t4.x), fmaf(s2, t3.y, -s1 * t4.y));
    X1 = make_float2(m1.x + u1.y, m1.y - u1.x);    // m1 - i*u1
    X4 = make_float2(m1.x - u1.y, m1.y + u1.x);    // m1 + i*u1
    X2 = make_float2(m2.x + u2.y, m2.y - u2.x);    // m2 - i*u2
    X3 = make_float2(m2.x - u2.y, m2.y + u2.x);    // m2 + i*u2
}

// Full 15-point DFT over n2 via PFA (15 = 3*5, CRT maps, no inter-twiddles).
// Inputs xv[j] = x[n2] with n2 = j (j<6) or j+3 (j>=6); n2 in {6,7,8} are zero.
__device__ __forceinline__ void dft15_pfa(const float2 xv[12], float2 A[15])
{
    const float2 Z = make_float2(0.f, 0.f);
    float2 y0[5], y1[5], y2[5];                    // y[ka][b]
    // input map n = (5a + 3b) mod 15
    dft3(xv[0], xv[5], xv[7],  y0[0], y1[0], y2[0]);   // b=0: n=0,5,10
    dft3(xv[3], Z,     xv[10], y0[1], y1[1], y2[1]);   // b=1: n=3,(8),13
    dft3(Z,     xv[8], xv[1],  y0[2], y1[2], y2[2]);   // b=2: n=(6),11,1
    dft3(xv[6], xv[11],xv[4],  y0[3], y1[3], y2[3]);   // b=3: n=9,14,4
    dft3(xv[9], xv[2], Z,      y0[4], y1[4], y2[4]);   // b=4: n=12,2,(7)
    // output map k = (10*ka + 6*kb) mod 15
    dft5(y0[0], y0[1], y0[2], y0[3], y0[4], A[0],  A[6],  A[12], A[3],  A[9]);
    dft5(y1[0], y1[1], y1[2], y1[3], y1[4], A[10], A[1],  A[7],  A[13], A[4]);
    dft5(y2[0], y2[1], y2[2], y2[3], y2[4], A[5],  A[11], A[2],  A[8],  A[14]);
}

// Per-lane butterfly constants: uniform (non-predicated) formulation.
// Stage H: u = other + sgn_H * v;  v = u * twf_H  (twf_H = 1 on lower lanes).
struct BT {
    float2 t16, t8, t4, t2, base;
    float g16, g8, g4, g2, g1;
};

__device__ __forceinline__ BT make_bt(int lane) {
    BT bt; float s, c;
    int m16 = (lane & 16) ? (lane & 15) : 0;
    int m8  = (lane &  8) ? (lane &  7) : 0;
    int m4  = (lane &  4) ? (lane &  3) : 0;
    int m2  = (lane &  2) ? (lane &  1) : 0;
    sincospif(-(float)m16 * (1.0f / 16.0f), &s, &c); bt.t16 = make_float2(c, s);
    sincospif(-(float)m8  * (1.0f /  8.0f), &s, &c); bt.t8  = make_float2(c, s);
    sincospif(-(float)m4  * (1.0f /  4.0f), &s, &c); bt.t4  = make_float2(c, s);
    sincospif(-(float)m2  * (1.0f /  2.0f), &s, &c); bt.t2  = make_float2(c, s);
    sincospif(-(float)lane * (1.0f / 240.0f), &s, &c); bt.base = make_float2(c, s);  // w480^lane
    bt.g16 = (lane & 16) ? -1.f : 1.f;
    bt.g8  = (lane &  8) ? -1.f : 1.f;
    bt.g4  = (lane &  4) ? -1.f : 1.f;
    bt.g2  = (lane &  2) ? -1.f : 1.f;
    bt.g1  = (lane &  1) ? -1.f : 1.f;
    return bt;
}

template<int H>
__device__ __forceinline__ void bfly_u(float2& v, float2 twf, float sgn) {
    float ox = __shfl_xor_sync(0xffffffffu, v.x, H);
    float oy = __shfl_xor_sync(0xffffffffu, v.y, H);
    float ux = fmaf(sgn, v.x, ox);
    float uy = fmaf(sgn, v.y, oy);
    v = cmulf(make_float2(ux, uy), twf);
}

// 32-pt FFT across lanes for one k2 slice (input v pre-twiddled). Output bit-reversed.
__device__ __forceinline__ float2 fft32_lanes(float2 v, const BT& bt)
{
    bfly_u<16>(v, bt.t16, bt.g16);
    bfly_u<8> (v, bt.t8,  bt.g8);
    bfly_u<4> (v, bt.t4,  bt.g4);
    bfly_u<2> (v, bt.t2,  bt.g2);
    float ox = __shfl_xor_sync(0xffffffffu, v.x, 1);
    float oy = __shfl_xor_sync(0xffffffffu, v.y, 1);
    return make_float2(fmaf(bt.g1, v.x, ox), fmaf(bt.g1, v.y, oy));
}

// Pass 1: FFT along Y for the 384 nonzero x-rows. One warp per row.
// Writes buf1[c][ky][x] via shared staging (coalesced 64B chunks).
__global__ __launch_bounds__(NT) void pass1_kernel(
    const float* __restrict__ img_re, const float* __restrict__ img_im)
{
    __shared__ float2 sh[GS * 9];      // [ky][8 rows], stride 9

    const int t = threadIdx.x, lane = t & 31, w = t >> 5;
    const int b = blockIdx.x;
    const int c = b / 48;
    const int g = b - c * 48;
    int x0 = g * 8; if (x0 >= 192) x0 += 96;       // valid x: [0,192) U [288,480)

    const int x = x0 + w;
    int px = x + HALF; if (px >= GS) px -= GS;
    const int ix = px - PAD;                        // in [0,384)
    const float* rre = img_re + (c * IMS + ix) * IMS;
    const float* rim = img_im + (c * IMS + ix) * IMS;

    float2 xv[12];
    #pragma unroll
    for (int j = 0; j < 12; j++) {
        int n2 = (j < 6) ? j : j + 3;
        int n = lane + 32 * n2;
        int py = n + HALF; if (py >= GS) py -= GS;
        int iy = py - PAD;                          // in [0,384)
        xv[j].x = rre[iy];
        xv[j].y = rim[iy];
    }

    float2 A[15];
    dft15_pfa(xv, A);

    const BT bt = make_bt(lane);
    const int k1 = (int)(__brev((unsigned)lane) >> 27);
    float2 tw = make_float2(1.f, 0.f);
    #pragma unroll
    for (int k2 = 0; k2 < 15; k2++) {
        float2 v = fft32_lanes(cmulf(A[k2], tw), bt);
        sh[(15 * k1 + k2) * 9 + w] = v;
        tw = cmulf(tw, bt.base);
    }
    __syncthreads();

    #pragma unroll
    for (int idx = t; idx < GS * 8; idx += NT) {
        int ky = idx >> 3, j = idx & 7;
        g_buf1[(c * GS + ky) * GS + x0 + j] = sh[ky * 9 + j];
    }
}

// Pass 2: FFT along X. Block = (ky, half); 8 warps = 8 channels of one ky row.
// Stages in shared, writes buf2[h][kx][ky][c8] as dense 64B runs.
__global__ __launch_bounds__(NT) void pass2_kernel()
{
    __shared__ float2 sh[GS * 9];      // [kx][8 channels], stride 9

    const int t = threadIdx.x, lane = t & 31, w = t >> 5;
    const int b = blockIdx.x;
    const int ky = b >> 1;
    const int h  = b & 1;
    const int c  = h * 8 + w;

    const float2* src = g_buf1 + (c * GS + ky) * GS;
    float2 xv[12];
    #pragma unroll
    for (int j = 0; j < 12; j++) {
        int n2 = (j < 6) ? j : j + 3;
        xv[j] = src[lane + 32 * n2];                // coalesced 256B per n2
    }

    float2 A[15];
    dft15_pfa(xv, A);

    const BT bt = make_bt(lane);
    const int k1 = (int)(__brev((unsigned)lane) >> 27);
    float2 tw = make_float2(1.0f / 480.0f, 0.f);    // ortho norm seed
    #pragma unroll
    for (int k2 = 0; k2 < 15; k2++) {
        float2 v = fft32_lanes(cmulf(A[k2], tw), bt);
        sh[(15 * k1 + k2) * 9 + w] = v;
        tw = cmulf(tw, bt.base);
    }
    __syncthreads();

    float2* dst = g_buf2 + h * HPLANE + ky * 8;     // [kx][ky][c8]
    #pragma unroll
    for (int idx = t; idx < GS * 8; idx += NT) {
        int kx = idx >> 3, lc = idx & 7;
        dst[kx * (GS * 8) + lc] = sh[kx * 9 + lc];  // 64B runs per kx
    }
}

// Gather v3: 8 lanes per point (fewer L1 wavefronts), smem transpose,
// coalesced STG.128 output.
__global__ __launch_bounds__(256) void gather_kernel(
    const float* __restrict__ trj, float* __restrict__ out)
{
    __shared__ float4 sh4[GPTS * 9];   // [point][chunk], stride 9

    const int t = threadIdx.x;
    const int base = blockIdx.x * GPTS;

    // Load phase: chunk q of point pl; q = h*4 + j.
    #pragma unroll
    for (int it = 0; it < 4; it++) {
        int pl = it * 32 + (t >> 3);
        int q  = t & 7;
        int kp = base + pl;
        int kc = (kp < KPTS) ? kp : (KPTS - 1);

        float tx = trj[2 * kc + 0];
        float ty = trj[2 * kc + 1];
        float fx = __fadd_rn(__fmul_rn(tx, 1.25f), 240.0f);
        float fy = __fadd_rn(__fmul_rn(ty, 1.25f), 240.0f);
        fx = fminf(fmaxf(fx, 0.0f), 479.0f);
        fy = fminf(fmaxf(fy, 0.0f), 479.0f);
        int ixg = (int)rintf(fx);
        int iyg = (int)rintf(fy);
        int ux = ixg + HALF; if (ux >= GS) ux -= GS;
        int uy = iyg + HALF; if (uy >= GS) uy -= GS;
        int u = (ux * GS + uy) * 8;                 // float2 offset in plane

        int h = q >> 2, j = q & 3;
        const float4* p4 = reinterpret_cast<const float4*>(g_buf2 + h * HPLANE + u);
        sh4[pl * 9 + q] = p4[j];
    }
    __syncthreads();

    // Write phase: 32 output rows (16 real + 16 imag) x 128 points, STG.128.
    const float* shf = reinterpret_cast<const float*>(sh4);
    #pragma unroll
    for (int it2 = 0; it2 < 4; it2++) {
        int oc = (t >> 5) + it2 * 8;
        int l  = t & 31;
        int k  = base + 4 * l;
        if (k < KPTS) {                             // KPTS % 4 == 0 -> whole float4 in range
            int reim = oc >> 4;
            int c    = oc & 15;
            int h    = c >> 3, c8 = c & 7;
            int q    = h * 4 + (c8 >> 1);
            int comp = ((c8 & 1) << 1) + reim;
            int o0   = q * 4 + comp;
            float4 v;
            v.x = shf[(4 * l + 0) * 36 + o0];
            v.y = shf[(4 * l + 1) * 36 + o0];
            v.z = shf[(4 * l + 2) * 36 + o0];
            v.w = shf[(4 * l + 3) * 36 + o0];
            *reinterpret_cast<float4*>(out + oc * KPTS + k) = v;
        }
    }
}

extern "C" void kernel_launch(void* const* d_in, const int* in_sizes, int n_in,
                              void* d_out, int out_size)
{
    const float* img_re = (const float*)d_in[0];   // (1,16,384,384)
    const float* img_im = (const float*)d_in[1];   // (1,16,384,384)
    const float* trj    = (const float*)d_in[2];   // (1,500000,2)
    float* out = (float*)d_out;                    // (2,1,16,500000)

    pass1_kernel<<<NCH * 48, NT>>>(img_re, img_im);
    pass2_kernel<<<GS * 2, NT>>>();
    gather_kernel<<<(KPTS + GPTS - 1) / GPTS, 256>>>(trj, out);
}